// round 15
// baseline (speedup 1.0000x reference)
#include <cuda_runtime.h>
#include <cuda_fp16.h>
#include <cstdint>
#include <math.h>

// ---------------- problem constants ----------------
constexpr int kTOK = 8192;
constexpr int kD   = 1024;
constexpr int kF   = 4096;
constexpr int kE   = 8;
constexpr int kASSIGN = kTOK * 2;

constexpr int BM = 128, BN = 256;
constexpr int BK2 = 32;
constexpr int STG = 4;
constexpr int KSPLIT2 = 2;                          // split-K for GEMM2
constexpr int A_STAGE_BYTES = BM * 80;              // 10240
constexpr int B_ROW_U32     = 264;
constexpr int B_STAGE_BYTES = 16 * B_ROW_U32 * 4;   // 16896
constexpr int STAGE_BYTES   = A_STAGE_BYTES + B_STAGE_BYTES;   // 27136
constexpr int SMEM_BYTES    = STG * STAGE_BYTES;               // 108544

// ---------------- device scratch ----------------
__device__ int   g_topk_e[kASSIGN];
__device__ float g_topk_w[kASSIGN];
__device__ int   g_counts[kE];
__device__ int   g_offsets[kE + 1];
__device__ int   g_cursors[kE];
__device__ int   g_tok[kASSIGN];
__device__ float g_wt[kASSIGN];
__device__ __half   g_h[(size_t)kASSIGN * kF];
__device__ uint32_t g_w1h[(size_t)kE * (kD / 2) * kF];
__device__ uint32_t g_w2h[(size_t)kE * (kF / 2) * kD];
__device__ uint32_t g_xh[(size_t)kTOK * (kD / 2)];

// ---------------- helpers ----------------
__device__ __forceinline__ void mma_f16(float* c, uint32_t a0, uint32_t a1,
                                        uint32_t a2, uint32_t a3,
                                        uint32_t b0, uint32_t b1) {
    asm volatile("mma.sync.aligned.m16n8k16.row.col.f32.f16.f16.f32 "
                 "{%0,%1,%2,%3}, {%4,%5,%6,%7}, {%8,%9}, {%0,%1,%2,%3};"
                 : "+f"(c[0]), "+f"(c[1]), "+f"(c[2]), "+f"(c[3])
                 : "r"(a0), "r"(a1), "r"(a2), "r"(a3), "r"(b0), "r"(b1));
}
__device__ __forceinline__ void ldmatrix_x4(uint32_t* r, uint32_t addr) {
    asm volatile("ldmatrix.sync.aligned.m8n8.x4.shared.b16 {%0,%1,%2,%3}, [%4];"
                 : "=r"(r[0]), "=r"(r[1]), "=r"(r[2]), "=r"(r[3]) : "r"(addr));
}
__device__ __forceinline__ uint32_t h2(float a, float b) {
    __half2 h = __floats2half2_rn(a, b);
    return *(uint32_t*)&h;
}
__device__ __forceinline__ float gelu_f(float v) {
    return 0.5f * v * (1.0f + erff(v * 0.70710678118654752f));
}
__device__ __forceinline__ uint32_t smem_u32(const void* p) {
    uint32_t a;
    asm("{ .reg .u64 t; cvta.to.shared.u64 t, %1; cvt.u32.u64 %0, t; }"
        : "=r"(a) : "l"(p));
    return a;
}
#define CP_ASYNC16(dst, src) \
    asm volatile("cp.async.cg.shared.global [%0], [%1], 16;" :: "r"(dst), "l"(src))
#define CP_ASYNC16Z(dst, src, sz) \
    asm volatile("cp.async.cg.shared.global [%0], [%1], 16, %2;" :: "r"(dst), "l"(src), "r"(sz))
#define CP_COMMIT() asm volatile("cp.async.commit_group;" ::: "memory")
#define CP_WAIT2()  asm volatile("cp.async.wait_group 2;" ::: "memory")
#define CP_WAIT1()  asm volatile("cp.async.wait_group 1;" ::: "memory")
#define CP_WAIT0()  asm volatile("cp.async.wait_group 0;" ::: "memory")
#define PIPE_WAIT(c, C2) do {                 \
    if ((c) + 1 == (C2))      { CP_WAIT0(); } \
    else if ((c) + 2 == (C2)) { CP_WAIT1(); } \
    else                      { CP_WAIT2(); } \
} while (0)

// ---------------- routing kernels ----------------
__global__ void init_kernel() {
    int i = threadIdx.x;
    if (i < kE) { g_counts[i] = 0; g_cursors[i] = 0; }
}

// gate + fused x->fp16 conversion
__global__ void gate_kernel(const float* __restrict__ x, const float* __restrict__ Wg,
                            const float* __restrict__ bg) {
    int w = (blockIdx.x * blockDim.x + threadIdx.x) >> 5;
    int lane = threadIdx.x & 31;
    if (w >= kTOK) return;
    const float* xr = x + (size_t)w * kD;
    uint32_t* xh = g_xh + (size_t)w * (kD / 2);
    float acc[kE];
#pragma unroll
    for (int e = 0; e < kE; e++) acc[e] = 0.f;
    for (int d = lane * 4; d < kD; d += 128) {
        float4 xv = *(const float4*)(xr + d);
        uint2 hv = make_uint2(h2(xv.x, xv.y), h2(xv.z, xv.w));
        *(uint2*)(xh + d / 2) = hv;
#pragma unroll
        for (int e = 0; e < kE; e++) {
            float4 wv = *(const float4*)(Wg + e * kD + d);
            acc[e] += xv.x * wv.x + xv.y * wv.y + xv.z * wv.z + xv.w * wv.w;
        }
    }
#pragma unroll
    for (int e = 0; e < kE; e++)
#pragma unroll
        for (int o = 16; o; o >>= 1) acc[e] += __shfl_xor_sync(0xffffffffu, acc[e], o);
    if (lane == 0) {
        float l[kE];
#pragma unroll
        for (int e = 0; e < kE; e++) l[e] = acc[e] + bg[e];
        int i1 = 0;
#pragma unroll
        for (int e = 1; e < kE; e++) if (l[e] > l[i1]) i1 = e;
        int i2 = (i1 == 0) ? 1 : 0;
#pragma unroll
        for (int e = 0; e < kE; e++) if (e != i1 && l[e] > l[i2]) i2 = e;
        float w1 = 1.f / (1.f + expf(l[i2] - l[i1]));
        g_topk_e[2 * w] = i1; g_topk_e[2 * w + 1] = i2;
        g_topk_w[2 * w] = w1; g_topk_w[2 * w + 1] = 1.f - w1;
        atomicAdd(&g_counts[i1], 1);
        atomicAdd(&g_counts[i2], 1);
    }
}

__global__ void scan_kernel() {
    int s = 0;
#pragma unroll
    for (int e = 0; e < kE; e++) { g_offsets[e] = s; s += g_counts[e]; }
    g_offsets[kE] = s;
}

__global__ void scatter_kernel() {
    int i = blockIdx.x * blockDim.x + threadIdx.x;
    if (i >= kASSIGN) return;
    int e = g_topk_e[i];
    int pos = g_offsets[e] + atomicAdd(&g_cursors[e], 1);
    g_tok[pos] = i >> 1;
    g_wt[pos] = g_topk_w[i];
}

// ---------------- merged weight conversion ----------------
constexpr int W1_BLOCKS = kE * (kD / 2) * (kF / 4) / 256;
constexpr int W2_BLOCKS = kE * (kF / 2) * (kD / 4) / 256;
__global__ void convert_w(const float* __restrict__ W1, const float* __restrict__ W2) {
    if (blockIdx.x < W1_BLOCKS) {
        int idx = blockIdx.x * blockDim.x + threadIdx.x;
        int n4 = idx & 1023;
        int r  = idx >> 10;
        int k2 = r & 511;
        int e  = r >> 9;
        const float* base = W1 + ((size_t)e * kD + 2 * k2) * kF + n4 * 4;
        float4 a = *(const float4*)base;
        float4 b = *(const float4*)(base + kF);
        uint4 o = make_uint4(h2(a.x, b.x), h2(a.y, b.y), h2(a.z, b.z), h2(a.w, b.w));
        *(uint4*)(g_w1h + ((size_t)e * (kD / 2) + k2) * kF + n4 * 4) = o;
    } else {
        int idx = (blockIdx.x - W1_BLOCKS) * blockDim.x + threadIdx.x;
        int n4 = idx & 255;
        int r  = idx >> 8;
        int k2 = r & 2047;
        int e  = r >> 11;
        const float* base = W2 + ((size_t)e * kF + 2 * k2) * kD + n4 * 4;
        float4 a = *(const float4*)base;
        float4 b = *(const float4*)(base + kD);
        uint4 o = make_uint4(h2(a.x, b.x), h2(a.y, b.y), h2(a.z, b.z), h2(a.w, b.w));
        *(uint4*)(g_w2h + ((size_t)e * (kF / 2) + k2) * kD + n4 * 4) = o;
    }
}

// ======================= fp16 mma.sync GEMM kernels ========================
// Tile 128(M) x 256(N), 8 warps (2M x 4N), warp tile 64x64.
// 4-stage cp.async ring, 3 chunks in flight, exact tail waits. (R10 config)

// ---------------- GEMM1: h = gelu(gather(xh) @ W1h + b1) -------------------
__global__ __launch_bounds__(256, 1) void gemm1_tc(const float* __restrict__ b1) {
    int e = blockIdx.z;
    int off = g_offsets[e];
    int cnt = g_offsets[e + 1] - off;
    int m0 = blockIdx.y * BM;
    if (m0 >= cnt) return;
    int n0 = blockIdx.x * BN;

    extern __shared__ __align__(16) char dsm[];
    uint32_t sb = smem_u32(dsm);
    __shared__ int stok[BM];

    int tid = threadIdx.x, wid = tid >> 5, lane = tid & 31;
    int tig = lane & 3, grp = lane >> 2;
    int mbase = (wid & 1) * 64;
    int nbase = (wid >> 1) * 64;

    if (tid < BM) {
        int m = m0 + tid;
        stok[tid] = (m < cnt) ? g_tok[off + m] : -1;
    }
    __syncthreads();

    int am = tid & 127;
    int t  = tid >> 7;
    int atok = stok[am];
    const uint32_t* asrc = g_xh + (size_t)((atok >= 0) ? atok : 0) * (kD / 2) + t * 8;
    uint32_t asz = (atok >= 0) ? 16u : 0u;
    uint32_t adst = sb + am * 80 + t * 32;
    int br = tid >> 4;
    int bj = tid & 15;
    const uint32_t* bsrc = g_w1h + ((size_t)e * (kD / 2) + br) * kF + n0 + bj * 4;
    uint32_t bdst = sb + A_STAGE_BYTES + br * (B_ROW_U32 * 4) + bj * 16;

    auto issue = [&](int st, int c) {
        uint32_t so = st * STAGE_BYTES;
        const uint32_t* as_ = asrc + c * 16;
        CP_ASYNC16Z(adst + so,      as_,     asz);
        CP_ASYNC16Z(adst + so + 16, as_ + 4, asz);
        const uint32_t* bs_ = bsrc + (size_t)c * 16 * kF;
#pragma unroll
        for (int q = 0; q < 4; q++)
            CP_ASYNC16(bdst + so + q * 256, bs_ + q * 64);
        CP_COMMIT();
    };

    int rowsel = lane & 15;
    int kh = lane >> 4;
    uint32_t a_lm0 = sb + (mbase + rowsel) * 80 + kh * 16;

    float acc[4][8][4];
#pragma unroll
    for (int i = 0; i < 4; i++)
#pragma unroll
        for (int j = 0; j < 8; j++)
#pragma unroll
            for (int q = 0; q < 4; q++) acc[i][j][q] = 0.f;

    constexpr int C2 = kD / BK2;   // 32
    issue(0, 0); issue(1, 1); issue(2, 2);

    for (int c = 0; c < C2; c++) {
        int st = c % STG;
        PIPE_WAIT(c, C2);
        __syncthreads();
        if (c + 3 < C2) issue((c + 3) % STG, c + 3);

        uint32_t so = st * STAGE_BYTES;
        const uint32_t* Bst = (const uint32_t*)(dsm + so + A_STAGE_BYTES);
#pragma unroll
        for (int p = 0; p < 2; p++) {
            uint32_t af[4][4], bf[8][2];
            uint32_t ab = a_lm0 + so + p * 32;
#pragma unroll
            for (int mt = 0; mt < 4; mt++)
                ldmatrix_x4(af[mt], ab + mt * 16 * 80);
#pragma unroll
            for (int nt = 0; nt < 8; nt++) {
                int nc = nbase + nt * 8 + grp;
                bf[nt][0] = Bst[(p * 8 + tig) * B_ROW_U32 + nc];
                bf[nt][1] = Bst[(p * 8 + tig + 4) * B_ROW_U32 + nc];
            }
#pragma unroll
            for (int mt = 0; mt < 4; mt++)
#pragma unroll
                for (int nt = 0; nt < 8; nt++)
                    mma_f16(acc[mt][nt], af[mt][0], af[mt][1], af[mt][2], af[mt][3],
                            bf[nt][0], bf[nt][1]);
        }
    }

    // epilogue: bias + gelu, write fp16
    const float* bb = b1 + (size_t)e * kF + n0;
#pragma unroll
    for (int mt = 0; mt < 4; mt++) {
        int rbase = mbase + mt * 16 + grp;
#pragma unroll
        for (int h = 0; h < 2; h++) {
            int r = rbase + h * 8;
            int m = m0 + r;
            if (m < cnt) {
                __half* hrow = g_h + (size_t)(off + m) * kF + n0;
#pragma unroll
                for (int nt = 0; nt < 8; nt++) {
                    int cc = nbase + nt * 8 + tig * 2;
                    float vx = gelu_f(acc[mt][nt][h * 2 + 0] + bb[cc]);
                    float vy = gelu_f(acc[mt][nt][h * 2 + 1] + bb[cc + 1]);
                    *(uint32_t*)(hrow + cc) = h2(vx, vy);
                }
            }
        }
    }
}

// ---------------- GEMM2: out += w * (h @ W2h + b2), SPLIT-K=2 --------------
// blockIdx.z = e * KSPLIT2 + s; split s covers K range [s*kF/2, (s+1)*kF/2).
// Bias added only by split 0. Accumulate via atomicAdd into zeroed out.
__global__ __launch_bounds__(256, 1) void gemm2_tc(const float* __restrict__ b2,
                                                   float* __restrict__ out) {
    int zz = blockIdx.z;
    int e  = zz >> 1;
    int sp = zz & 1;
    int off = g_offsets[e];
    int cnt = g_offsets[e + 1] - off;
    int m0 = blockIdx.y * BM;
    if (m0 >= cnt) return;
    int n0 = blockIdx.x * BN;

    extern __shared__ __align__(16) char dsm[];
    uint32_t sb = smem_u32(dsm);
    __shared__ int   stok[BM];
    __shared__ float swt[BM];

    int tid = threadIdx.x, wid = tid >> 5, lane = tid & 31;
    int tig = lane & 3, grp = lane >> 2;
    int mbase = (wid & 1) * 64;
    int nbase = (wid >> 1) * 64;

    if (tid < BM) {
        int m = m0 + tid;
        stok[tid] = (m < cnt) ? g_tok[off + m] : -1;
        swt[tid]  = (m < cnt) ? g_wt[off + m] : 0.f;
    }
    __syncthreads();

    constexpr int C2 = (kF / KSPLIT2) / BK2;   // 64 chunks per split
    const int c0 = sp * C2;                    // global chunk base

    int am = tid & 127;
    int t  = tid >> 7;
    bool avalid = (m0 + am) < cnt;
    const __half* asrc = g_h + (avalid ? (size_t)(off + m0 + am) * kF : 0) + t * 16;
    uint32_t asz = avalid ? 16u : 0u;
    uint32_t adst = sb + am * 80 + t * 32;
    int br = tid >> 4;
    int bj = tid & 15;
    const uint32_t* bsrc = g_w2h + ((size_t)e * (kF / 2) + br) * kD + n0 + bj * 4;
    uint32_t bdst = sb + A_STAGE_BYTES + br * (B_ROW_U32 * 4) + bj * 16;

    auto issue = [&](int st, int c) {
        uint32_t so = st * STAGE_BYTES;
        const __half* as_ = asrc + (size_t)(c0 + c) * 32;
        CP_ASYNC16Z(adst + so,      as_,     asz);
        CP_ASYNC16Z(adst + so + 16, as_ + 8, asz);
        const uint32_t* bs_ = bsrc + (size_t)(c0 + c) * 16 * kD;
#pragma unroll
        for (int q = 0; q < 4; q++)
            CP_ASYNC16(bdst + so + q * 256, bs_ + q * 64);
        CP_COMMIT();
    };

    int rowsel = lane & 15;
    int kh = lane >> 4;
    uint32_t a_lm0 = sb + (mbase + rowsel) * 80 + kh * 16;

    float acc[4][8][4];
#pragma unroll
    for (int i = 0; i < 4; i++)
#pragma unroll
        for (int j = 0; j < 8; j++)
#pragma unroll
            for (int q = 0; q < 4; q++) acc[i][j][q] = 0.f;

    issue(0, 0); issue(1, 1); issue(2, 2);

    for (int c = 0; c < C2; c++) {
        int st = c % STG;
        PIPE_WAIT(c, C2);
        __syncthreads();
        if (c + 3 < C2) issue((c + 3) % STG, c + 3);

        uint32_t so = st * STAGE_BYTES;
        const uint32_t* Bst = (const uint32_t*)(dsm + so + A_STAGE_BYTES);
#pragma unroll
        for (int p = 0; p < 2; p++) {
            uint32_t af[4][4], bf[8][2];
            uint32_t ab = a_lm0 + so + p * 32;
#pragma unroll
            for (int mt = 0; mt < 4; mt++)
                ldmatrix_x4(af[mt], ab + mt * 16 * 80);
#pragma unroll
            for (int nt = 0; nt < 8; nt++) {
                int nc = nbase + nt * 8 + grp;
                bf[nt][0] = Bst[(p * 8 + tig) * B_ROW_U32 + nc];
                bf[nt][1] = Bst[(p * 8 + tig + 4) * B_ROW_U32 + nc];
            }
#pragma unroll
            for (int mt = 0; mt < 4; mt++)
#pragma unroll
                for (int nt = 0; nt < 8; nt++)
                    mma_f16(acc[mt][nt], af[mt][0], af[mt][1], af[mt][2], af[mt][3],
                            bf[nt][0], bf[nt][1]);
        }
    }

    // epilogue: weighted atomic scatter; bias only from split 0
    const float* bbv = b2 + (size_t)e * kD + n0;
    float bscale = (sp == 0) ? 1.f : 0.f;
#pragma unroll
    for (int mt = 0; mt < 4; mt++) {
        int rbase = mbase + mt * 16 + grp;
#pragma unroll
        for (int h = 0; h < 2; h++) {
            int r = rbase + h * 8;
            int m = m0 + r;
            if (m < cnt) {
                int   tok = stok[r];
                float w   = swt[r];
                float* orow = out + (size_t)tok * kD + n0;
#pragma unroll
                for (int nt = 0; nt < 8; nt++) {
                    int cc = nbase + nt * 8 + tig * 2;
                    atomicAdd(&orow[cc],     w * (acc[mt][nt][h * 2 + 0] + bscale * bbv[cc]));
                    atomicAdd(&orow[cc + 1], w * (acc[mt][nt][h * 2 + 1] + bscale * bbv[cc + 1]));
                }
            }
        }
    }
}

// ---------------- launch ----------------
extern "C" void kernel_launch(void* const* d_in, const int* in_sizes, int n_in,
                              void* d_out, int out_size) {
    const float* x  = (const float*)d_in[0];
    const float* Wg = (const float*)d_in[1];
    const float* bg = (const float*)d_in[2];
    const float* W1 = (const float*)d_in[3];
    const float* b1 = (const float*)d_in[4];
    const float* W2 = (const float*)d_in[5];
    const float* b2 = (const float*)d_in[6];
    float* out = (float*)d_out;

    cudaFuncSetAttribute(gemm1_tc, cudaFuncAttributeMaxDynamicSharedMemorySize, SMEM_BYTES);
    cudaFuncSetAttribute(gemm2_tc, cudaFuncAttributeMaxDynamicSharedMemorySize, SMEM_BYTES);

    cudaMemsetAsync(out, 0, (size_t)out_size * sizeof(float));
    init_kernel<<<1, 32>>>();
    gate_kernel<<<kTOK / 8, 256>>>(x, Wg, bg);
    convert_w<<<W1_BLOCKS + W2_BLOCKS, 256>>>(W1, W2);
    scan_kernel<<<1, 1>>>();
    scatter_kernel<<<kASSIGN / 256, 256>>>();
    gemm1_tc<<<dim3(kF / BN, kTOK / BM, kE), 256, SMEM_BYTES>>>(b1);
    gemm2_tc<<<dim3(kD / BN, kTOK / BM, kE * KSPLIT2), 256, SMEM_BYTES>>>(b2, out);
}

// round 16
// speedup vs baseline: 1.0152x; 1.0152x over previous
#include <cuda_runtime.h>
#include <cuda_fp16.h>
#include <cstdint>
#include <math.h>

// ---------------- problem constants ----------------
constexpr int kTOK = 8192;
constexpr int kD   = 1024;
constexpr int kF   = 4096;
constexpr int kE   = 8;
constexpr int kASSIGN = kTOK * 2;

constexpr int BM = 128, BN = 256;
constexpr int BK2 = 32;
constexpr int STG = 4;
constexpr int A_STAGE_BYTES = BM * 80;              // 10240
constexpr int B_ROW_U32     = 264;
constexpr int B_STAGE_BYTES = 16 * B_ROW_U32 * 4;   // 16896
constexpr int STAGE_BYTES   = A_STAGE_BYTES + B_STAGE_BYTES;   // 27136
constexpr int SMEM_BYTES    = STG * STAGE_BYTES;               // 108544

constexpr int MAX_TILES = kASSIGN / BM + kE;        // 136 upper bound on real m-tiles

// ---------------- device scratch ----------------
__device__ int   g_topk_e[kASSIGN];
__device__ float g_topk_w[kASSIGN];
__device__ int   g_counts[kE];
__device__ int   g_offsets[kE + 1];
__device__ int   g_cursors[kE];
__device__ int   g_tok[kASSIGN];
__device__ float g_wt[kASSIGN];
__device__ int   g_tile_e[MAX_TILES];               // compact tile list: expert
__device__ int   g_tile_m[MAX_TILES];               // compact tile list: m0
__device__ int   g_ntiles;
__device__ __half   g_h[(size_t)kASSIGN * kF];
__device__ uint32_t g_w1h[(size_t)kE * (kD / 2) * kF];
__device__ uint32_t g_w2h[(size_t)kE * (kF / 2) * kD];
__device__ uint32_t g_xh[(size_t)kTOK * (kD / 2)];

// ---------------- helpers ----------------
__device__ __forceinline__ void mma_f16(float* c, uint32_t a0, uint32_t a1,
                                        uint32_t a2, uint32_t a3,
                                        uint32_t b0, uint32_t b1) {
    asm volatile("mma.sync.aligned.m16n8k16.row.col.f32.f16.f16.f32 "
                 "{%0,%1,%2,%3}, {%4,%5,%6,%7}, {%8,%9}, {%0,%1,%2,%3};"
                 : "+f"(c[0]), "+f"(c[1]), "+f"(c[2]), "+f"(c[3])
                 : "r"(a0), "r"(a1), "r"(a2), "r"(a3), "r"(b0), "r"(b1));
}
__device__ __forceinline__ void ldmatrix_x4(uint32_t* r, uint32_t addr) {
    asm volatile("ldmatrix.sync.aligned.m8n8.x4.shared.b16 {%0,%1,%2,%3}, [%4];"
                 : "=r"(r[0]), "=r"(r[1]), "=r"(r[2]), "=r"(r[3]) : "r"(addr));
}
__device__ __forceinline__ uint32_t h2(float a, float b) {
    __half2 h = __floats2half2_rn(a, b);
    return *(uint32_t*)&h;
}
__device__ __forceinline__ float gelu_f(float v) {
    return 0.5f * v * (1.0f + erff(v * 0.70710678118654752f));
}
__device__ __forceinline__ uint32_t smem_u32(const void* p) {
    uint32_t a;
    asm("{ .reg .u64 t; cvta.to.shared.u64 t, %1; cvt.u32.u64 %0, t; }"
        : "=r"(a) : "l"(p));
    return a;
}
#define CP_ASYNC16(dst, src) \
    asm volatile("cp.async.cg.shared.global [%0], [%1], 16;" :: "r"(dst), "l"(src))
#define CP_ASYNC16Z(dst, src, sz) \
    asm volatile("cp.async.cg.shared.global [%0], [%1], 16, %2;" :: "r"(dst), "l"(src), "r"(sz))
#define CP_COMMIT() asm volatile("cp.async.commit_group;" ::: "memory")
#define CP_WAIT2()  asm volatile("cp.async.wait_group 2;" ::: "memory")
#define CP_WAIT1()  asm volatile("cp.async.wait_group 1;" ::: "memory")
#define CP_WAIT0()  asm volatile("cp.async.wait_group 0;" ::: "memory")
#define PIPE_WAIT(c, C2) do {                 \
    if ((c) + 1 == (C2))      { CP_WAIT0(); } \
    else if ((c) + 2 == (C2)) { CP_WAIT1(); } \
    else                      { CP_WAIT2(); } \
} while (0)

// ---------------- routing kernels ----------------
__global__ void init_kernel() {
    int i = threadIdx.x;
    if (i < kE) { g_counts[i] = 0; g_cursors[i] = 0; }
}

// gate + fused x->fp16 conversion
__global__ void gate_kernel(const float* __restrict__ x, const float* __restrict__ Wg,
                            const float* __restrict__ bg) {
    int w = (blockIdx.x * blockDim.x + threadIdx.x) >> 5;
    int lane = threadIdx.x & 31;
    if (w >= kTOK) return;
    const float* xr = x + (size_t)w * kD;
    uint32_t* xh = g_xh + (size_t)w * (kD / 2);
    float acc[kE];
#pragma unroll
    for (int e = 0; e < kE; e++) acc[e] = 0.f;
    for (int d = lane * 4; d < kD; d += 128) {
        float4 xv = *(const float4*)(xr + d);
        uint2 hv = make_uint2(h2(xv.x, xv.y), h2(xv.z, xv.w));
        *(uint2*)(xh + d / 2) = hv;
#pragma unroll
        for (int e = 0; e < kE; e++) {
            float4 wv = *(const float4*)(Wg + e * kD + d);
            acc[e] += xv.x * wv.x + xv.y * wv.y + xv.z * wv.z + xv.w * wv.w;
        }
    }
#pragma unroll
    for (int e = 0; e < kE; e++)
#pragma unroll
        for (int o = 16; o; o >>= 1) acc[e] += __shfl_xor_sync(0xffffffffu, acc[e], o);
    if (lane == 0) {
        float l[kE];
#pragma unroll
        for (int e = 0; e < kE; e++) l[e] = acc[e] + bg[e];
        int i1 = 0;
#pragma unroll
        for (int e = 1; e < kE; e++) if (l[e] > l[i1]) i1 = e;
        int i2 = (i1 == 0) ? 1 : 0;
#pragma unroll
        for (int e = 0; e < kE; e++) if (e != i1 && l[e] > l[i2]) i2 = e;
        float w1 = 1.f / (1.f + expf(l[i2] - l[i1]));
        g_topk_e[2 * w] = i1; g_topk_e[2 * w + 1] = i2;
        g_topk_w[2 * w] = w1; g_topk_w[2 * w + 1] = 1.f - w1;
        atomicAdd(&g_counts[i1], 1);
        atomicAdd(&g_counts[i2], 1);
    }
}

// scan + compact tile-list construction (<=136 iterations, single thread)
__global__ void scan_kernel() {
    int s = 0, nt = 0;
#pragma unroll
    for (int e = 0; e < kE; e++) {
        g_offsets[e] = s;
        int cnt = g_counts[e];
        for (int m0 = 0; m0 < cnt; m0 += BM) {
            g_tile_e[nt] = e;
            g_tile_m[nt] = m0;
            nt++;
        }
        s += cnt;
    }
    g_offsets[kE] = s;
    g_ntiles = nt;
}

__global__ void scatter_kernel() {
    int i = blockIdx.x * blockDim.x + threadIdx.x;
    if (i >= kASSIGN) return;
    int e = g_topk_e[i];
    int pos = g_offsets[e] + atomicAdd(&g_cursors[e], 1);
    g_tok[pos] = i >> 1;
    g_wt[pos] = g_topk_w[i];
}

// ---------------- merged weight conversion ----------------
constexpr int W1_BLOCKS = kE * (kD / 2) * (kF / 4) / 256;
constexpr int W2_BLOCKS = kE * (kF / 2) * (kD / 4) / 256;
__global__ void convert_w(const float* __restrict__ W1, const float* __restrict__ W2) {
    if (blockIdx.x < W1_BLOCKS) {
        int idx = blockIdx.x * blockDim.x + threadIdx.x;
        int n4 = idx & 1023;
        int r  = idx >> 10;
        int k2 = r & 511;
        int e  = r >> 9;
        const float* base = W1 + ((size_t)e * kD + 2 * k2) * kF + n4 * 4;
        float4 a = *(const float4*)base;
        float4 b = *(const float4*)(base + kF);
        uint4 o = make_uint4(h2(a.x, b.x), h2(a.y, b.y), h2(a.z, b.z), h2(a.w, b.w));
        *(uint4*)(g_w1h + ((size_t)e * (kD / 2) + k2) * kF + n4 * 4) = o;
    } else {
        int idx = (blockIdx.x - W1_BLOCKS) * blockDim.x + threadIdx.x;
        int n4 = idx & 255;
        int r  = idx >> 8;
        int k2 = r & 2047;
        int e  = r >> 11;
        const float* base = W2 + ((size_t)e * kF + 2 * k2) * kD + n4 * 4;
        float4 a = *(const float4*)base;
        float4 b = *(const float4*)(base + kD);
        uint4 o = make_uint4(h2(a.x, b.x), h2(a.y, b.y), h2(a.z, b.z), h2(a.w, b.w));
        *(uint4*)(g_w2h + ((size_t)e * (kF / 2) + k2) * kD + n4 * 4) = o;
    }
}

// ======================= fp16 mma.sync GEMM kernels ========================
// Tile 128(M) x 256(N), 8 warps (2M x 4N), warp tile 64x64.
// 4-stage cp.async ring, 3 chunks in flight, exact tail waits.
// COMPACT GRID: blockIdx.y indexes the compact (expert, m0) tile list —
// no dead CTAs from the 8x m-tile over-provisioning.

// ---------------- GEMM1: h = gelu(gather(xh) @ W1h + b1) -------------------
__global__ __launch_bounds__(256, 1) void gemm1_tc(const float* __restrict__ b1) {
    int ti = blockIdx.y;
    if (ti >= g_ntiles) return;
    int e  = g_tile_e[ti];
    int m0 = g_tile_m[ti];
    int off = g_offsets[e];
    int cnt = g_offsets[e + 1] - off;
    int n0 = blockIdx.x * BN;

    extern __shared__ __align__(16) char dsm[];
    uint32_t sb = smem_u32(dsm);
    __shared__ int stok[BM];

    int tid = threadIdx.x, wid = tid >> 5, lane = tid & 31;
    int tig = lane & 3, grp = lane >> 2;
    int mbase = (wid & 1) * 64;
    int nbase = (wid >> 1) * 64;

    if (tid < BM) {
        int m = m0 + tid;
        stok[tid] = (m < cnt) ? g_tok[off + m] : -1;
    }
    __syncthreads();

    int am = tid & 127;
    int t  = tid >> 7;
    int atok = stok[am];
    const uint32_t* asrc = g_xh + (size_t)((atok >= 0) ? atok : 0) * (kD / 2) + t * 8;
    uint32_t asz = (atok >= 0) ? 16u : 0u;
    uint32_t adst = sb + am * 80 + t * 32;
    int br = tid >> 4;
    int bj = tid & 15;
    const uint32_t* bsrc = g_w1h + ((size_t)e * (kD / 2) + br) * kF + n0 + bj * 4;
    uint32_t bdst = sb + A_STAGE_BYTES + br * (B_ROW_U32 * 4) + bj * 16;

    auto issue = [&](int st, int c) {
        uint32_t so = st * STAGE_BYTES;
        const uint32_t* as_ = asrc + c * 16;
        CP_ASYNC16Z(adst + so,      as_,     asz);
        CP_ASYNC16Z(adst + so + 16, as_ + 4, asz);
        const uint32_t* bs_ = bsrc + (size_t)c * 16 * kF;
#pragma unroll
        for (int q = 0; q < 4; q++)
            CP_ASYNC16(bdst + so + q * 256, bs_ + q * 64);
        CP_COMMIT();
    };

    int rowsel = lane & 15;
    int kh = lane >> 4;
    uint32_t a_lm0 = sb + (mbase + rowsel) * 80 + kh * 16;

    float acc[4][8][4];
#pragma unroll
    for (int i = 0; i < 4; i++)
#pragma unroll
        for (int j = 0; j < 8; j++)
#pragma unroll
            for (int q = 0; q < 4; q++) acc[i][j][q] = 0.f;

    constexpr int C2 = kD / BK2;   // 32
    issue(0, 0); issue(1, 1); issue(2, 2);

    for (int c = 0; c < C2; c++) {
        int st = c % STG;
        PIPE_WAIT(c, C2);
        __syncthreads();
        if (c + 3 < C2) issue((c + 3) % STG, c + 3);

        uint32_t so = st * STAGE_BYTES;
        const uint32_t* Bst = (const uint32_t*)(dsm + so + A_STAGE_BYTES);
#pragma unroll
        for (int p = 0; p < 2; p++) {
            uint32_t af[4][4], bf[8][2];
            uint32_t ab = a_lm0 + so + p * 32;
#pragma unroll
            for (int mt = 0; mt < 4; mt++)
                ldmatrix_x4(af[mt], ab + mt * 16 * 80);
#pragma unroll
            for (int nt = 0; nt < 8; nt++) {
                int nc = nbase + nt * 8 + grp;
                bf[nt][0] = Bst[(p * 8 + tig) * B_ROW_U32 + nc];
                bf[nt][1] = Bst[(p * 8 + tig + 4) * B_ROW_U32 + nc];
            }
#pragma unroll
            for (int mt = 0; mt < 4; mt++)
#pragma unroll
                for (int nt = 0; nt < 8; nt++)
                    mma_f16(acc[mt][nt], af[mt][0], af[mt][1], af[mt][2], af[mt][3],
                            bf[nt][0], bf[nt][1]);
        }
    }

    // epilogue: bias + gelu, write fp16
    const float* bb = b1 + (size_t)e * kF + n0;
#pragma unroll
    for (int mt = 0; mt < 4; mt++) {
        int rbase = mbase + mt * 16 + grp;
#pragma unroll
        for (int h = 0; h < 2; h++) {
            int r = rbase + h * 8;
            int m = m0 + r;
            if (m < cnt) {
                __half* hrow = g_h + (size_t)(off + m) * kF + n0;
#pragma unroll
                for (int nt = 0; nt < 8; nt++) {
                    int cc = nbase + nt * 8 + tig * 2;
                    float vx = gelu_f(acc[mt][nt][h * 2 + 0] + bb[cc]);
                    float vy = gelu_f(acc[mt][nt][h * 2 + 1] + bb[cc + 1]);
                    *(uint32_t*)(hrow + cc) = h2(vx, vy);
                }
            }
        }
    }
}

// ---------------- GEMM2: out += w * (h @ W2h + b2) -------------------------
__global__ __launch_bounds__(256, 1) void gemm2_tc(const float* __restrict__ b2,
                                                   float* __restrict__ out) {
    int ti = blockIdx.y;
    if (ti >= g_ntiles) return;
    int e  = g_tile_e[ti];
    int m0 = g_tile_m[ti];
    int off = g_offsets[e];
    int cnt = g_offsets[e + 1] - off;
    int n0 = blockIdx.x * BN;

    extern __shared__ __align__(16) char dsm[];
    uint32_t sb = smem_u32(dsm);
    __shared__ int   stok[BM];
    __shared__ float swt[BM];

    int tid = threadIdx.x, wid = tid >> 5, lane = tid & 31;
    int tig = lane & 3, grp = lane >> 2;
    int mbase = (wid & 1) * 64;
    int nbase = (wid >> 1) * 64;

    if (tid < BM) {
        int m = m0 + tid;
        stok[tid] = (m < cnt) ? g_tok[off + m] : -1;
        swt[tid]  = (m < cnt) ? g_wt[off + m] : 0.f;
    }
    __syncthreads();

    int am = tid & 127;
    int t  = tid >> 7;
    bool avalid = (m0 + am) < cnt;
    const __half* asrc = g_h + (avalid ? (size_t)(off + m0 + am) * kF : 0) + t * 16;
    uint32_t asz = avalid ? 16u : 0u;
    uint32_t adst = sb + am * 80 + t * 32;
    int br = tid >> 4;
    int bj = tid & 15;
    const uint32_t* bsrc = g_w2h + ((size_t)e * (kF / 2) + br) * kD + n0 + bj * 4;
    uint32_t bdst = sb + A_STAGE_BYTES + br * (B_ROW_U32 * 4) + bj * 16;

    auto issue = [&](int st, int c) {
        uint32_t so = st * STAGE_BYTES;
        const __half* as_ = asrc + c * 32;
        CP_ASYNC16Z(adst + so,      as_,     asz);
        CP_ASYNC16Z(adst + so + 16, as_ + 8, asz);
        const uint32_t* bs_ = bsrc + (size_t)c * 16 * kD;
#pragma unroll
        for (int q = 0; q < 4; q++)
            CP_ASYNC16(bdst + so + q * 256, bs_ + q * 64);
        CP_COMMIT();
    };

    int rowsel = lane & 15;
    int kh = lane >> 4;
    uint32_t a_lm0 = sb + (mbase + rowsel) * 80 + kh * 16;

    float acc[4][8][4];
#pragma unroll
    for (int i = 0; i < 4; i++)
#pragma unroll
        for (int j = 0; j < 8; j++)
#pragma unroll
            for (int q = 0; q < 4; q++) acc[i][j][q] = 0.f;

    constexpr int C2 = kF / BK2;   // 128
    issue(0, 0); issue(1, 1); issue(2, 2);

    for (int c = 0; c < C2; c++) {
        int st = c % STG;
        PIPE_WAIT(c, C2);
        __syncthreads();
        if (c + 3 < C2) issue((c + 3) % STG, c + 3);

        uint32_t so = st * STAGE_BYTES;
        const uint32_t* Bst = (const uint32_t*)(dsm + so + A_STAGE_BYTES);
#pragma unroll
        for (int p = 0; p < 2; p++) {
            uint32_t af[4][4], bf[8][2];
            uint32_t ab = a_lm0 + so + p * 32;
#pragma unroll
            for (int mt = 0; mt < 4; mt++)
                ldmatrix_x4(af[mt], ab + mt * 16 * 80);
#pragma unroll
            for (int nt = 0; nt < 8; nt++) {
                int nc = nbase + nt * 8 + grp;
                bf[nt][0] = Bst[(p * 8 + tig) * B_ROW_U32 + nc];
                bf[nt][1] = Bst[(p * 8 + tig + 4) * B_ROW_U32 + nc];
            }
#pragma unroll
            for (int mt = 0; mt < 4; mt++)
#pragma unroll
                for (int nt = 0; nt < 8; nt++)
                    mma_f16(acc[mt][nt], af[mt][0], af[mt][1], af[mt][2], af[mt][3],
                            bf[nt][0], bf[nt][1]);
        }
    }

    // epilogue: weighted atomic scatter (fp32)
    const float* bbv = b2 + (size_t)e * kD + n0;
#pragma unroll
    for (int mt = 0; mt < 4; mt++) {
        int rbase = mbase + mt * 16 + grp;
#pragma unroll
        for (int h = 0; h < 2; h++) {
            int r = rbase + h * 8;
            int m = m0 + r;
            if (m < cnt) {
                int   tok = stok[r];
                float w   = swt[r];
                float* orow = out + (size_t)tok * kD + n0;
#pragma unroll
                for (int nt = 0; nt < 8; nt++) {
                    int cc = nbase + nt * 8 + tig * 2;
                    atomicAdd(&orow[cc],     w * (acc[mt][nt][h * 2 + 0] + bbv[cc]));
                    atomicAdd(&orow[cc + 1], w * (acc[mt][nt][h * 2 + 1] + bbv[cc + 1]));
                }
            }
        }
    }
}

// ---------------- launch ----------------
extern "C" void kernel_launch(void* const* d_in, const int* in_sizes, int n_in,
                              void* d_out, int out_size) {
    const float* x  = (const float*)d_in[0];
    const float* Wg = (const float*)d_in[1];
    const float* bg = (const float*)d_in[2];
    const float* W1 = (const float*)d_in[3];
    const float* b1 = (const float*)d_in[4];
    const float* W2 = (const float*)d_in[5];
    const float* b2 = (const float*)d_in[6];
    float* out = (float*)d_out;

    cudaFuncSetAttribute(gemm1_tc, cudaFuncAttributeMaxDynamicSharedMemorySize, SMEM_BYTES);
    cudaFuncSetAttribute(gemm2_tc, cudaFuncAttributeMaxDynamicSharedMemorySize, SMEM_BYTES);

    cudaMemsetAsync(out, 0, (size_t)out_size * sizeof(float));
    init_kernel<<<1, 32>>>();
    gate_kernel<<<kTOK / 8, 256>>>(x, Wg, bg);
    convert_w<<<W1_BLOCKS + W2_BLOCKS, 256>>>(W1, W2);
    scan_kernel<<<1, 1>>>();
    scatter_kernel<<<kASSIGN / 256, 256>>>();
    gemm1_tc<<<dim3(kF / BN, MAX_TILES), 256, SMEM_BYTES>>>(b1);
    gemm2_tc<<<dim3(kD / BN, MAX_TILES), 256, SMEM_BYTES>>>(b2, out);
}